// round 8
// baseline (speedup 1.0000x reference)
#include <cuda_runtime.h>
#include <cuda_fp16.h>
#include <cstdint>

// Problem constants (fixed-shape problem)
#define MAXN 100000
#define MAXE 1600000
#define DIN  128
#define DH   128
#define DOUT 16

// Scratch (device globals — no runtime allocation). 16B-aligned.
__device__ __align__(16) float  g_dinv[MAXN];
__device__ __align__(16) __half g_h16[MAXN * DH];   // h = x@W1 (unscaled), fp16
__device__ __align__(16) float  g_g  [MAXN * DOUT]; // g' = dinv * (h2@W2)
__device__ int g_cnt [MAXN];      // in-degree (excl. self-loop)
__device__ int g_rs  [MAXN];      // CSR row start
__device__ int g_cur [MAXN];      // fill cursor
__device__ int g_bsum[256];
__device__ int g_boff[256];
__device__ int g_csr [MAXE];      // src per edge, grouped by dst
__device__ int g_is64;            // edge_index dtype flag

__device__ __forceinline__ int load_idx(const void* __restrict__ ei, int i) {
    if (g_is64) return (int)((const long long*)ei)[i];
    return ((const int*)ei)[i];
}

// ---------------------------------------------------------------------------
// K0: zero degree counters + edge-index dtype probe
// ---------------------------------------------------------------------------
__global__ void k_init(const int* __restrict__ ei, int n) {
    int i = blockIdx.x * blockDim.x + threadIdx.x;
    if (i < n) g_cnt[i] = 0;
    if (i == 0) {
        int is64 = 1;
        for (int j = 1; j < 64; j += 2)
            if (ei[j] != 0) is64 = 0;
        g_is64 = is64;
    }
}

// ---------------------------------------------------------------------------
// K1 (fat): hist blocks first (tiny, retire fast), then GEMM1 tiles.
// GEMM1: h = x @ W1 (NO dinv), stored fp16.
// Tile 64 rows x 128 cols, K-chunks 32, block 256, thread = 4 rows x 8 cols.
// ---------------------------------------------------------------------------
__global__ void __launch_bounds__(256) k_gemm1_hist(
    const float* __restrict__ x, const float* __restrict__ W1,
    const void* __restrict__ ei, int n, int e, int histB) {

    if ((int)blockIdx.x < histB) {
        int i = blockIdx.x * 256 + threadIdx.x;
        if (i < e) atomicAdd(&g_cnt[load_idx(ei, e + i)], 1);
        return;
    }

    __shared__ float Xs[64][33];
    __shared__ float Ws[32][128];

    int tid  = threadIdx.x;
    int row0 = ((int)blockIdx.x - histB) * 64;
    int cx   = tid & 15;
    int ry   = tid >> 4;

    float acc[4][8];
#pragma unroll
    for (int i = 0; i < 4; i++)
#pragma unroll
        for (int j = 0; j < 8; j++) acc[i][j] = 0.0f;

    for (int k0 = 0; k0 < DIN; k0 += 32) {
        for (int i = tid; i < 64 * 32; i += 256) {
            int r = i >> 5, c = i & 31;
            int gr = row0 + r;
            Xs[r][c] = (gr < n) ? x[gr * DIN + k0 + c] : 0.0f;
        }
        for (int i = tid; i < 32 * 128; i += 256) {
            int r = i >> 7, c = i & 127;
            Ws[r][c] = W1[(k0 + r) * DH + c];
        }
        __syncthreads();

#pragma unroll
        for (int k = 0; k < 32; k++) {
            float a[4];
#pragma unroll
            for (int i = 0; i < 4; i++) a[i] = Xs[ry * 4 + i][k];
            const float4* bp = (const float4*)&Ws[k][cx * 8];
            float4 b0 = bp[0], b1v = bp[1];
            float b[8] = {b0.x, b0.y, b0.z, b0.w, b1v.x, b1v.y, b1v.z, b1v.w};
#pragma unroll
            for (int i = 0; i < 4; i++)
#pragma unroll
                for (int j = 0; j < 8; j++) acc[i][j] += a[i] * b[j];
        }
        __syncthreads();
    }

#pragma unroll
    for (int i = 0; i < 4; i++) {
        int r = row0 + ry * 4 + i;
        if (r < n) {
            __half2 p0 = __floats2half2_rn(acc[i][0], acc[i][1]);
            __half2 p1 = __floats2half2_rn(acc[i][2], acc[i][3]);
            __half2 p2 = __floats2half2_rn(acc[i][4], acc[i][5]);
            __half2 p3 = __floats2half2_rn(acc[i][6], acc[i][7]);
            uint4 pk;
            pk.x = *(uint32_t*)&p0; pk.y = *(uint32_t*)&p1;
            pk.z = *(uint32_t*)&p2; pk.w = *(uint32_t*)&p3;
            *(uint4*)&g_h16[r * DH + cx * 8] = pk;
        }
    }
}

// ---------------------------------------------------------------------------
// Exclusive scan of g_cnt -> g_rs (3 small kernels)
// ---------------------------------------------------------------------------
__global__ void k_scan_block(int n) {
    __shared__ int s[1024];
    int t = threadIdx.x;
    int i = blockIdx.x * 1024 + t;
    int v = (i < n) ? g_cnt[i] : 0;
    s[t] = v;
    __syncthreads();
#pragma unroll
    for (int off = 1; off < 1024; off <<= 1) {
        int u = (t >= off) ? s[t - off] : 0;
        __syncthreads();
        s[t] += u;
        __syncthreads();
    }
    if (i < n) g_rs[i] = s[t] - v;
    if (t == 1023) g_bsum[blockIdx.x] = s[1023];
}

__global__ void k_scan_tot(int nb) {
    __shared__ int s[128];
    int t = threadIdx.x;
    int v = (t < nb) ? g_bsum[t] : 0;
    s[t] = v;
    __syncthreads();
#pragma unroll
    for (int off = 1; off < 128; off <<= 1) {
        int u = (t >= off) ? s[t - off] : 0;
        __syncthreads();
        s[t] += u;
        __syncthreads();
    }
    if (t < nb) g_boff[t] = s[t] - v;
}

__global__ void k_scan_add(int n) {
    int i = blockIdx.x * blockDim.x + threadIdx.x;
    if (i < n) {
        g_rs[i] += g_boff[i >> 10];
        g_cur[i] = 0;
        g_dinv[i] = rsqrtf((float)(g_cnt[i] + 1));
    }
}

__global__ void k_fill(const void* __restrict__ ei, int e) {
    int i = blockIdx.x * blockDim.x + threadIdx.x;
    if (i < e) {
        int s = load_idx(ei, i);
        int d = load_idx(ei, e + i);
        int pos = g_rs[d] + atomicAdd(&g_cur[d], 1);
        g_csr[pos] = s;
    }
}

// ---------------------------------------------------------------------------
// K6 fused: layer-1 aggregation (fp16 sources, fp32 accum) + relu/bias +
// GEMM2 + dinv epilogue, one warp per node. Lane l owns h cols 4l..4l+3.
// g'[v] = dinv[v] * relu(dinv[v]*agg + b1) @ W2
// ---------------------------------------------------------------------------
__global__ void __launch_bounds__(256) k_agg_gemm2(
    const float* __restrict__ W2, const float* __restrict__ b1, int n) {

    __shared__ float Ws[128][16];
    int tid = threadIdx.x;
    for (int i = tid; i < DH * DOUT; i += 256) Ws[i >> 4][i & 15] = W2[i];
    __syncthreads();

    int w = ((int)blockIdx.x * 256 + tid) >> 5;
    int lane = tid & 31;
    if (w >= n) return;

    int row = g_rs[w];
    int deg = g_cnt[w];
    float dv = g_dinv[w];
    int col = lane * 4;

    // self-loop: dinv[v] * h[v]
    uint2 hv = *(const uint2*)&g_h16[w * DH + col];
    float2 a0 = __half22float2(*(__half2*)&hv.x);
    float2 a1 = __half22float2(*(__half2*)&hv.y);
    float4 acc = make_float4(dv * a0.x, dv * a0.y, dv * a1.x, dv * a1.y);

    int j = 0;
    for (; j + 1 < deg; j += 2) {
        int s0 = g_csr[row + j];
        int s1 = g_csr[row + j + 1];
        float d0 = g_dinv[s0], d1 = g_dinv[s1];
        uint2 h0 = *(const uint2*)&g_h16[s0 * DH + col];
        uint2 h1 = *(const uint2*)&g_h16[s1 * DH + col];
        float2 x0 = __half22float2(*(__half2*)&h0.x);
        float2 x1 = __half22float2(*(__half2*)&h0.y);
        float2 y0 = __half22float2(*(__half2*)&h1.x);
        float2 y1 = __half22float2(*(__half2*)&h1.y);
        acc.x += d0 * x0.x + d1 * y0.x;
        acc.y += d0 * x0.y + d1 * y0.y;
        acc.z += d0 * x1.x + d1 * y1.x;
        acc.w += d0 * x1.y + d1 * y1.y;
    }
    if (j < deg) {
        int s0 = g_csr[row + j];
        float d0 = g_dinv[s0];
        uint2 h0 = *(const uint2*)&g_h16[s0 * DH + col];
        float2 x0 = __half22float2(*(__half2*)&h0.x);
        float2 x1 = __half22float2(*(__half2*)&h0.y);
        acc.x += d0 * x0.x; acc.y += d0 * x0.y;
        acc.z += d0 * x1.x; acc.w += d0 * x1.y;
    }

    // h2 = relu(dinv[v]*agg + b1)
    float4 bb = *(const float4*)&b1[col];
    float h2[4];
    h2[0] = fmaxf(dv * acc.x + bb.x, 0.0f);
    h2[1] = fmaxf(dv * acc.y + bb.y, 0.0f);
    h2[2] = fmaxf(dv * acc.z + bb.z, 0.0f);
    h2[3] = fmaxf(dv * acc.w + bb.w, 0.0f);

    // partial GEMM2: lane's 4 k's against all 16 outputs
    float4 p0 = make_float4(0.f, 0.f, 0.f, 0.f);
    float4 p1 = make_float4(0.f, 0.f, 0.f, 0.f);
    float4 p2 = make_float4(0.f, 0.f, 0.f, 0.f);
    float4 p3 = make_float4(0.f, 0.f, 0.f, 0.f);
#pragma unroll
    for (int i = 0; i < 4; i++) {
        float a = h2[i];
        int k = col + i;
        float4 w0 = *(const float4*)&Ws[k][0];
        float4 w1 = *(const float4*)&Ws[k][4];
        float4 w2 = *(const float4*)&Ws[k][8];
        float4 w3 = *(const float4*)&Ws[k][12];
        p0.x += a * w0.x; p0.y += a * w0.y; p0.z += a * w0.z; p0.w += a * w0.w;
        p1.x += a * w1.x; p1.y += a * w1.y; p1.z += a * w1.z; p1.w += a * w1.w;
        p2.x += a * w2.x; p2.y += a * w2.y; p2.z += a * w2.z; p2.w += a * w2.w;
        p3.x += a * w3.x; p3.y += a * w3.y; p3.z += a * w3.z; p3.w += a * w3.w;
    }
    // butterfly reduce all 16 scalars across the warp
#pragma unroll
    for (int off = 1; off < 32; off <<= 1) {
        p0.x += __shfl_xor_sync(0xFFFFFFFF, p0.x, off);
        p0.y += __shfl_xor_sync(0xFFFFFFFF, p0.y, off);
        p0.z += __shfl_xor_sync(0xFFFFFFFF, p0.z, off);
        p0.w += __shfl_xor_sync(0xFFFFFFFF, p0.w, off);
        p1.x += __shfl_xor_sync(0xFFFFFFFF, p1.x, off);
        p1.y += __shfl_xor_sync(0xFFFFFFFF, p1.y, off);
        p1.z += __shfl_xor_sync(0xFFFFFFFF, p1.z, off);
        p1.w += __shfl_xor_sync(0xFFFFFFFF, p1.w, off);
        p2.x += __shfl_xor_sync(0xFFFFFFFF, p2.x, off);
        p2.y += __shfl_xor_sync(0xFFFFFFFF, p2.y, off);
        p2.z += __shfl_xor_sync(0xFFFFFFFF, p2.z, off);
        p2.w += __shfl_xor_sync(0xFFFFFFFF, p2.w, off);
        p3.x += __shfl_xor_sync(0xFFFFFFFF, p3.x, off);
        p3.y += __shfl_xor_sync(0xFFFFFFFF, p3.y, off);
        p3.z += __shfl_xor_sync(0xFFFFFFFF, p3.z, off);
        p3.w += __shfl_xor_sync(0xFFFFFFFF, p3.w, off);
    }
    if (lane < 4) {
        float4 sel = (lane == 0) ? p0 : (lane == 1) ? p1 : (lane == 2) ? p2 : p3;
        sel.x *= dv; sel.y *= dv; sel.z *= dv; sel.w *= dv;
        *(float4*)&g_g[w * DOUT + lane * 4] = sel;
    }
}

// ---------------------------------------------------------------------------
// Gather layer 2 + epilogue: warp per node, 8 edges/iter x 4 lanes x float4.
// out[v] = dinv[v]*(g'[v] + sum g'[src]) + b2
// ---------------------------------------------------------------------------
__global__ void k_gather2(const float* __restrict__ b2,
                          float* __restrict__ out, int n) {
    int w = (blockIdx.x * blockDim.x + threadIdx.x) >> 5;
    int lane = threadIdx.x & 31;
    if (w >= n) return;
    int row = g_rs[w];
    int deg = g_cnt[w];
    int g = lane >> 2;
    int c = lane & 3;

    float4 acc = make_float4(0.f, 0.f, 0.f, 0.f);
    for (int base = 0; base < deg; base += 8) {
        int j = base + g;
        if (j < deg) {
            int s = g_csr[row + j];
            float4 v = *(const float4*)&g_g[s * DOUT + c * 4];
            acc.x += v.x; acc.y += v.y; acc.z += v.z; acc.w += v.w;
        }
    }
#pragma unroll
    for (int off = 4; off < 32; off <<= 1) {
        acc.x += __shfl_xor_sync(0xFFFFFFFF, acc.x, off);
        acc.y += __shfl_xor_sync(0xFFFFFFFF, acc.y, off);
        acc.z += __shfl_xor_sync(0xFFFFFFFF, acc.z, off);
        acc.w += __shfl_xor_sync(0xFFFFFFFF, acc.w, off);
    }
    if (lane < 4) {
        float4 self = *(const float4*)&g_g[w * DOUT + c * 4];
        float4 bb   = *(const float4*)&b2[c * 4];
        float dv = g_dinv[w];
        float4 o;
        o.x = dv * (acc.x + self.x) + bb.x;
        o.y = dv * (acc.y + self.y) + bb.y;
        o.z = dv * (acc.z + self.z) + bb.z;
        o.w = dv * (acc.w + self.w) + bb.w;
        *(float4*)&out[w * DOUT + c * 4] = o;
    }
}

// ---------------------------------------------------------------------------
extern "C" void kernel_launch(void* const* d_in, const int* in_sizes, int n_in,
                              void* d_out, int out_size) {
    const float* x  = (const float*)d_in[0];
    const void*  ei = d_in[1];
    const float* W1 = (const float*)d_in[2];
    const float* b1 = (const float*)d_in[3];
    const float* W2 = (const float*)d_in[4];
    const float* b2 = (const float*)d_in[5];
    float*       out = (float*)d_out;

    int n = in_sizes[0] / DIN;   // 100000
    int e = in_sizes[1] / 2;     // 1600000
    int nb = (n + 1023) >> 10;   // scan blocks
    int histB = (e + 255) / 256; // 6250
    int gemmB = (n + 63) / 64;   // 1563

    // K0: zero counters + dtype probe
    k_init<<<(n + 255) / 256, 256>>>((const int*)ei, n);

    // K1: hist (first, retires fast) overlapped with GEMM1 (h fp16, no dinv)
    k_gemm1_hist<<<histB + gemmB, 256>>>(x, W1, ei, n, e, histB);

    // CSR finalize
    k_scan_block<<<nb, 1024>>>(n);
    k_scan_tot<<<1, 128>>>(nb);
    k_scan_add<<<(n + 255) / 256, 256>>>(n);
    k_fill<<<(e + 255) / 256, 256>>>(ei, e);

    // Fused: gather1 + relu/bias + GEMM2 + dinv -> g_g
    k_agg_gemm2<<<(n * 32 + 255) / 256, 256>>>(W2, b1, n);

    // Layer-2 gather + epilogue -> out
    k_gather2<<<(n * 32 + 255) / 256, 256>>>(b2, out, n);
}

// round 9
// speedup vs baseline: 1.5364x; 1.5364x over previous
#include <cuda_runtime.h>
#include <cuda_fp16.h>
#include <cstdint>

// Problem constants (fixed-shape problem)
#define MAXN 100000
#define MAXE 1600000
#define DIN  128
#define DH   128
#define DOUT 16

// Scratch (device globals — no runtime allocation). 16B-aligned.
__device__ __align__(16) float  g_dinv [MAXN];
__device__ __align__(16) __half g_h16  [MAXN * DH];   // h' = dinv*(x@W1), fp16
__device__ __align__(16) __half g_agg16[MAXN * DH];   // layer-1 aggregation, fp16
__device__ __align__(16) float  g_g    [MAXN * DOUT]; // g' = dinv*(h2@W2)
__device__ int g_cnt [MAXN];
__device__ int g_rs  [MAXN];
__device__ int g_cur [MAXN];
__device__ int g_bsum[256];
__device__ int g_boff[256];
__device__ int g_csr [MAXE];
__device__ int g_is64;

__device__ __forceinline__ int load_idx(const void* __restrict__ ei, int i) {
    if (g_is64) return (int)((const long long*)ei)[i];
    return ((const int*)ei)[i];
}

// ---------------------------------------------------------------------------
// K0: zero degree counters + edge-index dtype probe
// ---------------------------------------------------------------------------
__global__ void k_init(const int* __restrict__ ei, int n) {
    int i = blockIdx.x * blockDim.x + threadIdx.x;
    if (i < n) g_cnt[i] = 0;
    if (i == 0) {
        int is64 = 1;
        for (int j = 1; j < 64; j += 2)
            if (ei[j] != 0) is64 = 0;
        g_is64 = is64;
    }
}

__global__ void k_hist(const void* __restrict__ ei, int e) {
    int i = blockIdx.x * blockDim.x + threadIdx.x;
    if (i < e) atomicAdd(&g_cnt[load_idx(ei, e + i)], 1);
}

// ---------------------------------------------------------------------------
// Exclusive scan of g_cnt -> g_rs; dinv
// ---------------------------------------------------------------------------
__global__ void k_scan_block(int n) {
    __shared__ int s[1024];
    int t = threadIdx.x;
    int i = blockIdx.x * 1024 + t;
    int v = (i < n) ? g_cnt[i] : 0;
    s[t] = v;
    __syncthreads();
#pragma unroll
    for (int off = 1; off < 1024; off <<= 1) {
        int u = (t >= off) ? s[t - off] : 0;
        __syncthreads();
        s[t] += u;
        __syncthreads();
    }
    if (i < n) g_rs[i] = s[t] - v;
    if (t == 1023) g_bsum[blockIdx.x] = s[1023];
}

__global__ void k_scan_tot(int nb) {
    __shared__ int s[128];
    int t = threadIdx.x;
    int v = (t < nb) ? g_bsum[t] : 0;
    s[t] = v;
    __syncthreads();
#pragma unroll
    for (int off = 1; off < 128; off <<= 1) {
        int u = (t >= off) ? s[t - off] : 0;
        __syncthreads();
        s[t] += u;
        __syncthreads();
    }
    if (t < nb) g_boff[t] = s[t] - v;
}

__global__ void k_scan_add(int n) {
    int i = blockIdx.x * blockDim.x + threadIdx.x;
    if (i < n) {
        g_rs[i] += g_boff[i >> 10];
        g_cur[i] = 0;
        g_dinv[i] = rsqrtf((float)(g_cnt[i] + 1));
    }
}

__global__ void k_fill(const void* __restrict__ ei, int e) {
    int i = blockIdx.x * blockDim.x + threadIdx.x;
    if (i < e) {
        int s = load_idx(ei, i);
        int d = load_idx(ei, e + i);
        int pos = g_rs[d] + atomicAdd(&g_cur[d], 1);
        g_csr[pos] = s;
    }
}

// ---------------------------------------------------------------------------
// GEMM1: h' = dinv * (x @ W1), stored fp16.
// Tile 64 rows x 128 cols, K-chunks 32, block 256, thread = 4 rows x 8 cols.
// ---------------------------------------------------------------------------
__global__ void __launch_bounds__(256) k_gemm1(
    const float* __restrict__ x, const float* __restrict__ W1, int n) {
    __shared__ float Xs[64][33];
    __shared__ float Ws[32][128];

    int tid  = threadIdx.x;
    int row0 = blockIdx.x * 64;
    int cx   = tid & 15;
    int ry   = tid >> 4;

    float acc[4][8];
#pragma unroll
    for (int i = 0; i < 4; i++)
#pragma unroll
        for (int j = 0; j < 8; j++) acc[i][j] = 0.0f;

    for (int k0 = 0; k0 < DIN; k0 += 32) {
        for (int i = tid; i < 64 * 32; i += 256) {
            int r = i >> 5, c = i & 31;
            int gr = row0 + r;
            Xs[r][c] = (gr < n) ? x[gr * DIN + k0 + c] : 0.0f;
        }
        for (int i = tid; i < 32 * 128; i += 256) {
            int r = i >> 7, c = i & 127;
            Ws[r][c] = W1[(k0 + r) * DH + c];
        }
        __syncthreads();

#pragma unroll
        for (int k = 0; k < 32; k++) {
            float a[4];
#pragma unroll
            for (int i = 0; i < 4; i++) a[i] = Xs[ry * 4 + i][k];
            const float4* bp = (const float4*)&Ws[k][cx * 8];
            float4 b0 = bp[0], b1v = bp[1];
            float b[8] = {b0.x, b0.y, b0.z, b0.w, b1v.x, b1v.y, b1v.z, b1v.w};
#pragma unroll
            for (int i = 0; i < 4; i++)
#pragma unroll
                for (int j = 0; j < 8; j++) acc[i][j] += a[i] * b[j];
        }
        __syncthreads();
    }

#pragma unroll
    for (int i = 0; i < 4; i++) {
        int r = row0 + ry * 4 + i;
        if (r < n) {
            float dv = g_dinv[r];
            __half2 p0 = __floats2half2_rn(dv * acc[i][0], dv * acc[i][1]);
            __half2 p1 = __floats2half2_rn(dv * acc[i][2], dv * acc[i][3]);
            __half2 p2 = __floats2half2_rn(dv * acc[i][4], dv * acc[i][5]);
            __half2 p3 = __floats2half2_rn(dv * acc[i][6], dv * acc[i][7]);
            uint4 pk;
            pk.x = *(uint32_t*)&p0; pk.y = *(uint32_t*)&p1;
            pk.z = *(uint32_t*)&p2; pk.w = *(uint32_t*)&p3;
            *(uint4*)&g_h16[r * DH + cx * 8] = pk;
        }
    }
}

// ---------------------------------------------------------------------------
// Gather layer 1: half-warp per node (2 nodes/warp). Sub-lane owns 8 halfs
// (uint4 = LDG.128). agg[v] = h'[v] + sum h'[src], fp32 accum, fp16 store.
// ---------------------------------------------------------------------------
__global__ void k_gather1(int n) {
    int gw = (blockIdx.x * blockDim.x + threadIdx.x) >> 5;   // warp id
    int lane = threadIdx.x & 31;
    int w = gw * 2 + (lane >> 4);       // node
    int sub = lane & 15;                 // 0..15, owns 8 cols
    if (w >= n) return;
    int row = g_rs[w];
    int deg = g_cnt[w];
    const __half* hp = g_h16 + sub * 8;

    // self-loop
    uint4 hv = *(const uint4*)&hp[w * DH];
    float2 f0 = __half22float2(*(__half2*)&hv.x);
    float2 f1 = __half22float2(*(__half2*)&hv.y);
    float2 f2 = __half22float2(*(__half2*)&hv.z);
    float2 f3 = __half22float2(*(__half2*)&hv.w);
    float a0 = f0.x, a1 = f0.y, a2 = f1.x, a3 = f1.y;
    float a4 = f2.x, a5 = f2.y, a6 = f3.x, a7 = f3.y;

    int j = 0;
    for (; j + 1 < deg; j += 2) {
        int s0 = g_csr[row + j];
        int s1 = g_csr[row + j + 1];
        uint4 u0 = *(const uint4*)&hp[s0 * DH];
        uint4 u1 = *(const uint4*)&hp[s1 * DH];
        float2 x0 = __half22float2(*(__half2*)&u0.x);
        float2 x1 = __half22float2(*(__half2*)&u0.y);
        float2 x2 = __half22float2(*(__half2*)&u0.z);
        float2 x3 = __half22float2(*(__half2*)&u0.w);
        float2 y0 = __half22float2(*(__half2*)&u1.x);
        float2 y1 = __half22float2(*(__half2*)&u1.y);
        float2 y2 = __half22float2(*(__half2*)&u1.z);
        float2 y3 = __half22float2(*(__half2*)&u1.w);
        a0 += x0.x + y0.x; a1 += x0.y + y0.y;
        a2 += x1.x + y1.x; a3 += x1.y + y1.y;
        a4 += x2.x + y2.x; a5 += x2.y + y2.y;
        a6 += x3.x + y3.x; a7 += x3.y + y3.y;
    }
    if (j < deg) {
        int s0 = g_csr[row + j];
        uint4 u0 = *(const uint4*)&hp[s0 * DH];
        float2 x0 = __half22float2(*(__half2*)&u0.x);
        float2 x1 = __half22float2(*(__half2*)&u0.y);
        float2 x2 = __half22float2(*(__half2*)&u0.z);
        float2 x3 = __half22float2(*(__half2*)&u0.w);
        a0 += x0.x; a1 += x0.y; a2 += x1.x; a3 += x1.y;
        a4 += x2.x; a5 += x2.y; a6 += x3.x; a7 += x3.y;
    }

    __half2 p0 = __floats2half2_rn(a0, a1);
    __half2 p1 = __floats2half2_rn(a2, a3);
    __half2 p2 = __floats2half2_rn(a4, a5);
    __half2 p3 = __floats2half2_rn(a6, a7);
    uint4 pk;
    pk.x = *(uint32_t*)&p0; pk.y = *(uint32_t*)&p1;
    pk.z = *(uint32_t*)&p2; pk.w = *(uint32_t*)&p3;
    *(uint4*)&g_agg16[w * DH + sub * 8] = pk;
}

// ---------------------------------------------------------------------------
// GEMM2 fused: h2 = relu(dinv*agg + b1); g' = dinv * (h2 @ W2) -> g_g
// ---------------------------------------------------------------------------
__global__ void __launch_bounds__(256) k_gemm2(
    const float* __restrict__ W2, const float* __restrict__ b1, int n) {
    __shared__ float Hs[64][129];
    __shared__ float Ws[128][16];

    int tid  = threadIdx.x;
    int row0 = blockIdx.x * 64;

    for (int i = tid; i < DH * DOUT; i += 256) Ws[i >> 4][i & 15] = W2[i];

    // stage: 4 halfs (uint2) per task -> relu(dinv*agg+b1)
    for (int t = tid; t < 64 * DH / 4; t += 256) {
        int r = t >> 5, c4 = (t & 31) * 4;
        int gr = row0 + r;
        float v0 = 0.f, v1 = 0.f, v2 = 0.f, v3 = 0.f;
        if (gr < n) {
            float dv = g_dinv[gr];
            uint2 u = *(const uint2*)&g_agg16[gr * DH + c4];
            float2 q0 = __half22float2(*(__half2*)&u.x);
            float2 q1 = __half22float2(*(__half2*)&u.y);
            float4 bb = *(const float4*)&b1[c4];
            v0 = fmaxf(dv * q0.x + bb.x, 0.f);
            v1 = fmaxf(dv * q0.y + bb.y, 0.f);
            v2 = fmaxf(dv * q1.x + bb.z, 0.f);
            v3 = fmaxf(dv * q1.y + bb.w, 0.f);
        }
        Hs[r][c4] = v0; Hs[r][c4 + 1] = v1;
        Hs[r][c4 + 2] = v2; Hs[r][c4 + 3] = v3;
    }
    __syncthreads();

    int r  = tid >> 2;
    int j4 = tid & 3;
    int gr = row0 + r;
    if (gr >= n) return;

    float4 acc = make_float4(0.f, 0.f, 0.f, 0.f);
#pragma unroll
    for (int k = 0; k < DH; k++) {
        float a = Hs[r][k];
        float4 wv = *(const float4*)&Ws[k][j4 * 4];
        acc.x += a * wv.x; acc.y += a * wv.y;
        acc.z += a * wv.z; acc.w += a * wv.w;
    }
    float dv = g_dinv[gr];
    acc.x *= dv; acc.y *= dv; acc.z *= dv; acc.w *= dv;
    *(float4*)&g_g[gr * DOUT + j4 * 4] = acc;
}

// ---------------------------------------------------------------------------
// Gather layer 2 + epilogue: warp per node, 8 edges/iter x 4 lanes x float4.
// out[v] = dinv[v]*(g'[v] + sum g'[src]) + b2
// ---------------------------------------------------------------------------
__global__ void k_gather2(const float* __restrict__ b2,
                          float* __restrict__ out, int n) {
    int w = (blockIdx.x * blockDim.x + threadIdx.x) >> 5;
    int lane = threadIdx.x & 31;
    if (w >= n) return;
    int row = g_rs[w];
    int deg = g_cnt[w];
    int g = lane >> 2;
    int c = lane & 3;

    float4 acc = make_float4(0.f, 0.f, 0.f, 0.f);
    for (int base = 0; base < deg; base += 8) {
        int j = base + g;
        if (j < deg) {
            int s = g_csr[row + j];
            float4 v = *(const float4*)&g_g[s * DOUT + c * 4];
            acc.x += v.x; acc.y += v.y; acc.z += v.z; acc.w += v.w;
        }
    }
#pragma unroll
    for (int off = 4; off < 32; off <<= 1) {
        acc.x += __shfl_xor_sync(0xFFFFFFFF, acc.x, off);
        acc.y += __shfl_xor_sync(0xFFFFFFFF, acc.y, off);
        acc.z += __shfl_xor_sync(0xFFFFFFFF, acc.z, off);
        acc.w += __shfl_xor_sync(0xFFFFFFFF, acc.w, off);
    }
    if (lane < 4) {
        float4 self = *(const float4*)&g_g[w * DOUT + c * 4];
        float4 bb   = *(const float4*)&b2[c * 4];
        float dv = g_dinv[w];
        float4 o;
        o.x = dv * (acc.x + self.x) + bb.x;
        o.y = dv * (acc.y + self.y) + bb.y;
        o.z = dv * (acc.z + self.z) + bb.z;
        o.w = dv * (acc.w + self.w) + bb.w;
        *(float4*)&out[w * DOUT + c * 4] = o;
    }
}

// ---------------------------------------------------------------------------
extern "C" void kernel_launch(void* const* d_in, const int* in_sizes, int n_in,
                              void* d_out, int out_size) {
    const float* x  = (const float*)d_in[0];
    const void*  ei = d_in[1];
    const float* W1 = (const float*)d_in[2];
    const float* b1 = (const float*)d_in[3];
    const float* W2 = (const float*)d_in[4];
    const float* b2 = (const float*)d_in[5];
    float*       out = (float*)d_out;

    int n = in_sizes[0] / DIN;   // 100000
    int e = in_sizes[1] / 2;     // 1600000
    int nb = (n + 1023) >> 10;

    k_init<<<(n + 255) / 256, 256>>>((const int*)ei, n);
    k_hist<<<(e + 255) / 256, 256>>>(ei, e);
    k_scan_block<<<nb, 1024>>>(n);
    k_scan_tot<<<1, 128>>>(nb);
    k_scan_add<<<(n + 255) / 256, 256>>>(n);
    k_fill<<<(e + 255) / 256, 256>>>(ei, e);

    k_gemm1<<<(n + 63) / 64, 256>>>(x, W1, n);
    {
        int warps = (n + 1) / 2;
        k_gather1<<<(warps * 32 + 255) / 256, 256>>>(n);
    }
    k_gemm2<<<(n + 63) / 64, 256>>>(W2, b1, n);
    k_gather2<<<(n * 32 + 255) / 256, 256>>>(b2, out, n);
}

// round 10
// speedup vs baseline: 1.8709x; 1.2177x over previous
#include <cuda_runtime.h>
#include <cuda_fp16.h>
#include <cstdint>

// Problem constants (fixed-shape problem)
#define MAXN 100000
#define MAXE 1600000
#define DIN  128
#define DH   128
#define DOUT 16

// Scratch (device globals — no runtime allocation). 16B-aligned.
__device__ __align__(16) float  g_dinv [MAXN];
__device__ __align__(16) __half g_h16  [MAXN * DH];   // h' = dinv*(x@W1), fp16
__device__ __align__(16) __half g_agg16[MAXN * DH];   // layer-1 aggregation, fp16
__device__ __align__(16) float  g_g    [MAXN * DOUT]; // g' = dinv*(h2@W2)
__device__ __align__(16) __half g_wthi [DIN * DH];    // W1^T hi fp16, [n][k]
__device__ __align__(16) __half g_wtlo [DIN * DH];    // W1^T lo fp16, [n][k]
__device__ int g_cnt [MAXN];
__device__ int g_rs  [MAXN];
__device__ int g_cur [MAXN];
__device__ int g_bsum[256];
__device__ int g_boff[256];
__device__ int g_csr [MAXE];
__device__ int g_is64;

__device__ __forceinline__ int load_idx(const void* __restrict__ ei, int i) {
    if (g_is64) return (int)((const long long*)ei)[i];
    return ((const int*)ei)[i];
}

__device__ __forceinline__ uint32_t smem_u32(const void* p) {
    uint32_t a;
    asm("{ .reg .u64 t; cvta.to.shared.u64 t, %1; cvt.u32.u64 %0, t; }"
        : "=r"(a) : "l"(p));
    return a;
}

// ---------------------------------------------------------------------------
// K0: zero degree counters + edge-index dtype probe
// ---------------------------------------------------------------------------
__global__ void k_init(const int* __restrict__ ei, int n) {
    int i = blockIdx.x * blockDim.x + threadIdx.x;
    if (i < n) g_cnt[i] = 0;
    if (i == 0) {
        int is64 = 1;
        for (int j = 1; j < 64; j += 2)
            if (ei[j] != 0) is64 = 0;
        g_is64 = is64;
    }
}

__global__ void k_hist(const void* __restrict__ ei, int e) {
    int i = blockIdx.x * blockDim.x + threadIdx.x;
    if (i < e) atomicAdd(&g_cnt[load_idx(ei, e + i)], 1);
}

// ---------------------------------------------------------------------------
// Exclusive scan of g_cnt -> g_rs; dinv
// ---------------------------------------------------------------------------
__global__ void k_scan_block(int n) {
    __shared__ int s[1024];
    int t = threadIdx.x;
    int i = blockIdx.x * 1024 + t;
    int v = (i < n) ? g_cnt[i] : 0;
    s[t] = v;
    __syncthreads();
#pragma unroll
    for (int off = 1; off < 1024; off <<= 1) {
        int u = (t >= off) ? s[t - off] : 0;
        __syncthreads();
        s[t] += u;
        __syncthreads();
    }
    if (i < n) g_rs[i] = s[t] - v;
    if (t == 1023) g_bsum[blockIdx.x] = s[1023];
}

__global__ void k_scan_tot(int nb) {
    __shared__ int s[128];
    int t = threadIdx.x;
    int v = (t < nb) ? g_bsum[t] : 0;
    s[t] = v;
    __syncthreads();
#pragma unroll
    for (int off = 1; off < 128; off <<= 1) {
        int u = (t >= off) ? s[t - off] : 0;
        __syncthreads();
        s[t] += u;
        __syncthreads();
    }
    if (t < nb) g_boff[t] = s[t] - v;
}

__global__ void k_scan_add(int n) {
    int i = blockIdx.x * blockDim.x + threadIdx.x;
    if (i < n) {
        g_rs[i] += g_boff[i >> 10];
        g_cur[i] = 0;
        g_dinv[i] = rsqrtf((float)(g_cnt[i] + 1));
    }
}

__global__ void k_fill(const void* __restrict__ ei, int e) {
    int i = blockIdx.x * blockDim.x + threadIdx.x;
    if (i < e) {
        int s = load_idx(ei, i);
        int d = load_idx(ei, e + i);
        int pos = g_rs[d] + atomicAdd(&g_cur[d], 1);
        g_csr[pos] = s;
    }
}

// ---------------------------------------------------------------------------
// W1 prep: split fp32 -> fp16 hi/lo and transpose to [n][k] (k contiguous)
// ---------------------------------------------------------------------------
__global__ void k_prepw(const float* __restrict__ W1) {
    int i = blockIdx.x * 256 + threadIdx.x;
    if (i >= DIN * DH) return;
    int k = i >> 7, nn = i & 127;     // W1[k][nn]
    float v = W1[i];
    __half h = __float2half(v);
    __half l = __float2half(v - __half2float(h));
    g_wthi[nn * DIN + k] = h;
    g_wtlo[nn * DIN + k] = l;
}

// ---------------------------------------------------------------------------
// GEMM1 on tensor cores (mma.sync m16n8k16, fp16 split-precision 3 passes):
// h' = dinv * (x @ W1), stored fp16.
// CTA tile 64x128, full K=128 in smem. 8 warps = 2(M) x 4(N), warp m32 x n32.
// Smem rows padded to 136 halfs (272B) -> LDSM rows hit distinct banks.
// ---------------------------------------------------------------------------
#define APAD 136
#define A_HI_OFF 0
#define A_LO_OFF 17408
#define W_HI_OFF 34816
#define W_LO_OFF 69632
#define SM1_TOT  104448

__global__ void __launch_bounds__(256) k_gemm1_mma(
    const float* __restrict__ x, int n) {
    extern __shared__ char smem[];
    uint32_t sb = smem_u32(smem);
    int tid = threadIdx.x, wid = tid >> 5, lane = tid & 31;
    int row0 = blockIdx.x * 64;
    int wm = wid & 1, wn = wid >> 1;

    // stage W^T hi/lo with pad-insertion (L2-resident source)
    for (int t = tid; t < 128 * 16; t += 256) {
        int r = t >> 4, c = t & 15;
        *(uint4*)(smem + W_HI_OFF + r * 272 + c * 16) =
            *(const uint4*)&g_wthi[r * DIN + c * 8];
        *(uint4*)(smem + W_LO_OFF + r * 272 + c * 16) =
            *(const uint4*)&g_wtlo[r * DIN + c * 8];
    }

    // stage A: load x fp32, split into fp16 hi/lo
    for (int t = tid; t < 64 * 16; t += 256) {
        int r = t >> 4, c8 = (t & 15) * 8;
        int gr = row0 + r;
        float v[8];
        if (gr < n) {
            float4 f0 = *(const float4*)&x[gr * DIN + c8];
            float4 f1 = *(const float4*)&x[gr * DIN + c8 + 4];
            v[0] = f0.x; v[1] = f0.y; v[2] = f0.z; v[3] = f0.w;
            v[4] = f1.x; v[5] = f1.y; v[6] = f1.z; v[7] = f1.w;
        } else {
#pragma unroll
            for (int q = 0; q < 8; q++) v[q] = 0.0f;
        }
        uint32_t hw[4], lw[4];
#pragma unroll
        for (int q = 0; q < 4; q++) {
            __half2 h2 = __floats2half2_rn(v[2 * q], v[2 * q + 1]);
            float2 hf = __half22float2(h2);
            __half2 l2 = __floats2half2_rn(v[2 * q] - hf.x, v[2 * q + 1] - hf.y);
            hw[q] = *(uint32_t*)&h2;
            lw[q] = *(uint32_t*)&l2;
        }
        *(uint4*)(smem + A_HI_OFF + r * 272 + c8 * 2) = make_uint4(hw[0], hw[1], hw[2], hw[3]);
        *(uint4*)(smem + A_LO_OFF + r * 272 + c8 * 2) = make_uint4(lw[0], lw[1], lw[2], lw[3]);
    }
    __syncthreads();

    // ldmatrix thread offsets (within region), k-step advances by 32B
    int rowb = lane & 7, blk = lane >> 3;
    uint32_t offA[2], offB[2];
#pragma unroll
    for (int mi = 0; mi < 2; mi++) {
        int ml = wm * 32 + mi * 16 + (blk & 1) * 8 + rowb;
        int kl = (blk >> 1) * 8;
        offA[mi] = (uint32_t)(ml * APAD + kl) * 2;
    }
#pragma unroll
    for (int p = 0; p < 2; p++) {
        int nl = wn * 32 + p * 16 + (blk >> 1) * 8 + rowb;
        int kl = (blk & 1) * 8;
        offB[p] = (uint32_t)(nl * APAD + kl) * 2;
    }

    float acc[2][4][4];
#pragma unroll
    for (int mi = 0; mi < 2; mi++)
#pragma unroll
        for (int nj = 0; nj < 4; nj++)
#pragma unroll
            for (int q = 0; q < 4; q++) acc[mi][nj][q] = 0.0f;

    const uint32_t aBase[3] = { sb + A_HI_OFF, sb + A_LO_OFF, sb + A_HI_OFF };
    const uint32_t bBase[3] = { sb + W_HI_OFF, sb + W_HI_OFF, sb + W_LO_OFF };

#pragma unroll
    for (int pass = 0; pass < 3; pass++) {
        uint32_t ab = aBase[pass], bb = bBase[pass];
#pragma unroll
        for (int ks = 0; ks < 8; ks++) {
            uint32_t kofs = (uint32_t)ks * 32;
            uint32_t a[2][4], b[2][4];
#pragma unroll
            for (int mi = 0; mi < 2; mi++)
                asm volatile("ldmatrix.sync.aligned.m8n8.x4.shared.b16 {%0,%1,%2,%3}, [%4];"
                             : "=r"(a[mi][0]), "=r"(a[mi][1]), "=r"(a[mi][2]), "=r"(a[mi][3])
                             : "r"(ab + offA[mi] + kofs));
#pragma unroll
            for (int p = 0; p < 2; p++)
                asm volatile("ldmatrix.sync.aligned.m8n8.x4.shared.b16 {%0,%1,%2,%3}, [%4];"
                             : "=r"(b[p][0]), "=r"(b[p][1]), "=r"(b[p][2]), "=r"(b[p][3])
                             : "r"(bb + offB[p] + kofs));
#pragma unroll
            for (int mi = 0; mi < 2; mi++)
#pragma unroll
                for (int nj = 0; nj < 4; nj++) {
                    uint32_t b0 = b[nj >> 1][(nj & 1) * 2];
                    uint32_t b1 = b[nj >> 1][(nj & 1) * 2 + 1];
                    asm volatile(
                        "mma.sync.aligned.m16n8k16.row.col.f32.f16.f16.f32 "
                        "{%0,%1,%2,%3}, {%4,%5,%6,%7}, {%8,%9}, {%0,%1,%2,%3};"
                        : "+f"(acc[mi][nj][0]), "+f"(acc[mi][nj][1]),
                          "+f"(acc[mi][nj][2]), "+f"(acc[mi][nj][3])
                        : "r"(a[mi][0]), "r"(a[mi][1]), "r"(a[mi][2]), "r"(a[mi][3]),
                          "r"(b0), "r"(b1));
                }
        }
    }

    // epilogue: dinv scale, pack half2, store h'
    int qr = lane >> 2, qc = (lane & 3) * 2;
#pragma unroll
    for (int mi = 0; mi < 2; mi++) {
        int r0 = row0 + wm * 32 + mi * 16 + qr;
        int r1 = r0 + 8;
        float dv0 = (r0 < n) ? g_dinv[r0] : 0.0f;
        float dv1 = (r1 < n) ? g_dinv[r1] : 0.0f;
#pragma unroll
        for (int nj = 0; nj < 4; nj++) {
            int col = wn * 32 + nj * 8 + qc;
            if (r0 < n) {
                __half2 p = __floats2half2_rn(dv0 * acc[mi][nj][0], dv0 * acc[mi][nj][1]);
                *(__half2*)&g_h16[r0 * DH + col] = p;
            }
            if (r1 < n) {
                __half2 p = __floats2half2_rn(dv1 * acc[mi][nj][2], dv1 * acc[mi][nj][3]);
                *(__half2*)&g_h16[r1 * DH + col] = p;
            }
        }
    }
}

// ---------------------------------------------------------------------------
// Gather layer 1: half-warp per node (2 nodes/warp). Sub-lane owns 8 halfs
// (uint4 = LDG.128). agg[v] = h'[v] + sum h'[src], fp32 accum, fp16 store.
// ---------------------------------------------------------------------------
__global__ void k_gather1(int n) {
    int gw = (blockIdx.x * blockDim.x + threadIdx.x) >> 5;
    int lane = threadIdx.x & 31;
    int w = gw * 2 + (lane >> 4);
    int sub = lane & 15;
    if (w >= n) return;
    int row = g_rs[w];
    int deg = g_cnt[w];
    const __half* hp = g_h16 + sub * 8;

    uint4 hv = *(const uint4*)&hp[w * DH];
    float2 f0 = __half22float2(*(__half2*)&hv.x);
    float2 f1 = __half22float2(*(__half2*)&hv.y);
    float2 f2 = __half22float2(*(__half2*)&hv.z);
    float2 f3 = __half22float2(*(__half2*)&hv.w);
    float a0 = f0.x, a1 = f0.y, a2 = f1.x, a3 = f1.y;
    float a4 = f2.x, a5 = f2.y, a6 = f3.x, a7 = f3.y;

    int j = 0;
    for (; j + 1 < deg; j += 2) {
        int s0 = g_csr[row + j];
        int s1 = g_csr[row + j + 1];
        uint4 u0 = *(const uint4*)&hp[s0 * DH];
        uint4 u1 = *(const uint4*)&hp[s1 * DH];
        float2 x0 = __half22float2(*(__half2*)&u0.x);
        float2 x1 = __half22float2(*(__half2*)&u0.y);
        float2 x2 = __half22float2(*(__half2*)&u0.z);
        float2 x3 = __half22float2(*(__half2*)&u0.w);
        float2 y0 = __half22float2(*(__half2*)&u1.x);
        float2 y1 = __half22float2(*(__half2*)&u1.y);
        float2 y2 = __half22float2(*(__half2*)&u1.z);
        float2 y3 = __half22float2(*(__half2*)&u1.w);
        a0 += x0.x + y0.x; a1 += x0.y + y0.y;
        a2 += x1.x + y1.x; a3 += x1.y + y1.y;
        a4 += x2.x + y2.x; a5 += x2.y + y2.y;
        a6 += x3.x + y3.x; a7 += x3.y + y3.y;
    }
    if (j < deg) {
        int s0 = g_csr[row + j];
        uint4 u0 = *(const uint4*)&hp[s0 * DH];
        float2 x0 = __half22float2(*(__half2*)&u0.x);
        float2 x1 = __half22float2(*(__half2*)&u0.y);
        float2 x2 = __half22float2(*(__half2*)&u0.z);
        float2 x3 = __half22float2(*(__half2*)&u0.w);
        a0 += x0.x; a1 += x0.y; a2 += x1.x; a3 += x1.y;
        a4 += x2.x; a5 += x2.y; a6 += x3.x; a7 += x3.y;
    }

    __half2 p0 = __floats2half2_rn(a0, a1);
    __half2 p1 = __floats2half2_rn(a2, a3);
    __half2 p2 = __floats2half2_rn(a4, a5);
    __half2 p3 = __floats2half2_rn(a6, a7);
    uint4 pk;
    pk.x = *(uint32_t*)&p0; pk.y = *(uint32_t*)&p1;
    pk.z = *(uint32_t*)&p2; pk.w = *(uint32_t*)&p3;
    *(uint4*)&g_agg16[w * DH + sub * 8] = pk;
}

// ---------------------------------------------------------------------------
// GEMM2 fused: h2 = relu(dinv*agg + b1); g' = dinv * (h2 @ W2) -> g_g
// ---------------------------------------------------------------------------
__global__ void __launch_bounds__(256) k_gemm2(
    const float* __restrict__ W2, const float* __restrict__ b1, int n) {
    __shared__ float Hs[64][129];
    __shared__ float Ws[128][16];

    int tid  = threadIdx.x;
    int row0 = blockIdx.x * 64;

    for (int i = tid; i < DH * DOUT; i += 256) Ws[i >> 4][i & 15] = W2[i];

    for (int t = tid; t < 64 * DH / 4; t += 256) {
        int r = t >> 5, c4 = (t & 31) * 4;
        int gr = row0 + r;
        float v0 = 0.f, v1 = 0.f, v2 = 0.f, v3 = 0.f;
        if (gr < n) {
            float dv = g_dinv[gr];
            uint2 u = *(const uint2*)&g_agg16[gr * DH + c4];
            float2 q0 = __half22float2(*(__half2*)&u.x);
            float2 q1 = __half22float2(*(__half2*)&u.y);
            float4 bb = *(const float4*)&b1[c4];
            v0 = fmaxf(dv * q0.x + bb.x, 0.f);
            v1 = fmaxf(dv * q0.y + bb.y, 0.f);
            v2 = fmaxf(dv * q1.x + bb.z, 0.f);
            v3 = fmaxf(dv * q1.y + bb.w, 0.f);
        }
        Hs[r][c4] = v0; Hs[r][c4 + 1] = v1;
        Hs[r][c4 + 2] = v2; Hs[r][c4 + 3] = v3;
    }
    __syncthreads();

    int r  = tid >> 2;
    int j4 = tid & 3;
    int gr = row0 + r;
    if (gr >= n) return;

    float4 acc = make_float4(0.f, 0.f, 0.f, 0.f);
#pragma unroll
    for (int k = 0; k < DH; k++) {
        float a = Hs[r][k];
        float4 wv = *(const float4*)&Ws[k][j4 * 4];
        acc.x += a * wv.x; acc.y += a * wv.y;
        acc.z += a * wv.z; acc.w += a * wv.w;
    }
    float dv = g_dinv[gr];
    acc.x *= dv; acc.y *= dv; acc.z *= dv; acc.w *= dv;
    *(float4*)&g_g[gr * DOUT + j4 * 4] = acc;
}

// ---------------------------------------------------------------------------
// Gather layer 2 + epilogue: warp per node, 8 edges/iter x 4 lanes x float4.
// out[v] = dinv[v]*(g'[v] + sum g'[src]) + b2
// ---------------------------------------------------------------------------
__global__ void k_gather2(const float* __restrict__ b2,
                          float* __restrict__ out, int n) {
    int w = (blockIdx.x * blockDim.x + threadIdx.x) >> 5;
    int lane = threadIdx.x & 31;
    if (w >= n) return;
    int row = g_rs[w];
    int deg = g_cnt[w];
    int g = lane >> 2;
    int c = lane & 3;

    float4 acc = make_float4(0.f, 0.f, 0.f, 0.f);
    for (int base = 0; base < deg; base += 8) {
        int j = base + g;
        if (j < deg) {
            int s = g_csr[row + j];
            float4 v = *(const float4*)&g_g[s * DOUT + c * 4];
            acc.x += v.x; acc.y += v.y; acc.z += v.z; acc.w += v.w;
        }
    }
#pragma unroll
    for (int off = 4; off < 32; off <<= 1) {
        acc.x += __shfl_xor_sync(0xFFFFFFFF, acc.x, off);
        acc.y += __shfl_xor_sync(0xFFFFFFFF, acc.y, off);
        acc.z += __shfl_xor_sync(0xFFFFFFFF, acc.z, off);
        acc.w += __shfl_xor_sync(0xFFFFFFFF, acc.w, off);
    }
    if (lane < 4) {
        float4 self = *(const float4*)&g_g[w * DOUT + c * 4];
        float4 bb   = *(const float4*)&b2[c * 4];
        float dv = g_dinv[w];
        float4 o;
        o.x = dv * (acc.x + self.x) + bb.x;
        o.y = dv * (acc.y + self.y) + bb.y;
        o.z = dv * (acc.z + self.z) + bb.z;
        o.w = dv * (acc.w + self.w) + bb.w;
        *(float4*)&out[w * DOUT + c * 4] = o;
    }
}

// ---------------------------------------------------------------------------
extern "C" void kernel_launch(void* const* d_in, const int* in_sizes, int n_in,
                              void* d_out, int out_size) {
    const float* x  = (const float*)d_in[0];
    const void*  ei = d_in[1];
    const float* W1 = (const float*)d_in[2];
    const float* b1 = (const float*)d_in[3];
    const float* W2 = (const float*)d_in[4];
    const float* b2 = (const float*)d_in[5];
    float*       out = (float*)d_out;

    int n = in_sizes[0] / DIN;   // 100000
    int e = in_sizes[1] / 2;     // 1600000
    int nb = (n + 1023) >> 10;

    static int smem_set = 0;
    if (!smem_set) {
        cudaFuncSetAttribute(k_gemm1_mma,
                             cudaFuncAttributeMaxDynamicSharedMemorySize, SM1_TOT);
        smem_set = 1;
    }

    k_init<<<(n + 255) / 256, 256>>>((const int*)ei, n);
    k_hist<<<(e + 255) / 256, 256>>>(ei, e);
    k_scan_block<<<nb, 1024>>>(n);
    k_scan_tot<<<1, 128>>>(nb);
    k_scan_add<<<(n + 255) / 256, 256>>>(n);
    k_fill<<<(e + 255) / 256, 256>>>(ei, e);

    k_prepw<<<64, 256>>>(W1);
    k_gemm1_mma<<<(n + 63) / 64, 256, SM1_TOT>>>(x, n);
    {
        int warps = (n + 1) / 2;
        k_gather1<<<(warps * 32 + 255) / 256, 256>>>(n);
    }
    k_gemm2<<<(n + 63) / 64, 256>>>(W2, b1, n);
    k_gather2<<<(n * 32 + 255) / 256, 256>>>(b2, out, n);
}

// round 16
// speedup vs baseline: 1.8896x; 1.0100x over previous
#include <cuda_runtime.h>
#include <cuda_fp16.h>
#include <cstdint>

// Problem constants (fixed-shape problem)
#define MAXN 100000
#define MAXE 1600000
#define DIN  128
#define DH   128
#define DOUT 16

// Scratch (device globals — no runtime allocation). 16B-aligned.
__device__ __align__(16) float  g_dinv [MAXN];
__device__ __align__(16) __half g_h16  [MAXN * DH];   // h' = dinv*(x@W1), fp16
__device__ __align__(16) __half g_agg16[MAXN * DH];   // layer-1 aggregation, fp16
__device__ __align__(16) float  g_g    [MAXN * DOUT]; // g' = dinv*(h2@W2)
__device__ __align__(16) __half g_wthi [DIN * DH];    // W1^T hi fp16, [n][k]
__device__ __align__(16) __half g_wtlo [DIN * DH];    // W1^T lo fp16, [n][k]
__device__ int g_cnt [MAXN];
__device__ int g_rs  [MAXN];
__device__ int g_cur [MAXN];
__device__ int g_bsum[256];
__device__ int g_boff[256];
__device__ int g_csr [MAXE];
__device__ int g_is64;

__device__ __forceinline__ int load_idx(const void* __restrict__ ei, int i) {
    if (g_is64) return (int)((const long long*)ei)[i];
    return ((const int*)ei)[i];
}

__device__ __forceinline__ uint32_t smem_u32(const void* p) {
    uint32_t a;
    asm("{ .reg .u64 t; cvta.to.shared.u64 t, %1; cvt.u32.u64 %0, t; }"
        : "=r"(a) : "l"(p));
    return a;
}

// ---------------------------------------------------------------------------
// K0: zero degree counters + W1 split/transpose prep + dtype probe
// ---------------------------------------------------------------------------
__global__ void k_init(const int* __restrict__ ei, const float* __restrict__ W1,
                       int n) {
    int i = blockIdx.x * blockDim.x + threadIdx.x;
    if (i < n) g_cnt[i] = 0;
    if (i < DIN * DH) {
        int k = i >> 7, nn = i & 127;     // W1[k][nn]
        float v = W1[i];
        __half h = __float2half(v);
        __half l = __float2half(v - __half2float(h));
        g_wthi[nn * DIN + k] = h;
        g_wtlo[nn * DIN + k] = l;
    }
    if (i == 0) {
        int is64 = 1;
        for (int j = 1; j < 64; j += 2)
            if (ei[j] != 0) is64 = 0;
        g_is64 = is64;
    }
}

__global__ void k_hist(const void* __restrict__ ei, int e) {
    int i = blockIdx.x * blockDim.x + threadIdx.x;
    if (i < e) atomicAdd(&g_cnt[load_idx(ei, e + i)], 1);
}

// ---------------------------------------------------------------------------
// Exclusive scan of g_cnt -> g_rs (3 small kernels, proven safe) + dinv
// ---------------------------------------------------------------------------
__global__ void k_scan_block(int n) {
    __shared__ int s[1024];
    int t = threadIdx.x;
    int i = blockIdx.x * 1024 + t;
    int v = (i < n) ? g_cnt[i] : 0;
    s[t] = v;
    __syncthreads();
#pragma unroll
    for (int off = 1; off < 1024; off <<= 1) {
        int u = (t >= off) ? s[t - off] : 0;
        __syncthreads();
        s[t] += u;
        __syncthreads();
    }
    if (i < n) g_rs[i] = s[t] - v;
    if (t == 1023) g_bsum[blockIdx.x] = s[1023];
}

__global__ void k_scan_tot(int nb) {
    __shared__ int s[128];
    int t = threadIdx.x;
    int v = (t < nb) ? g_bsum[t] : 0;
    s[t] = v;
    __syncthreads();
#pragma unroll
    for (int off = 1; off < 128; off <<= 1) {
        int u = (t >= off) ? s[t - off] : 0;
        __syncthreads();
        s[t] += u;
        __syncthreads();
    }
    if (t < nb) g_boff[t] = s[t] - v;
}

__global__ void k_scan_add(int n) {
    int i = blockIdx.x * blockDim.x + threadIdx.x;
    if (i < n) {
        g_rs[i] += g_boff[i >> 10];
        g_cur[i] = 0;
        g_dinv[i] = rsqrtf((float)(g_cnt[i] + 1));
    }
}

__global__ void k_fill(const void* __restrict__ ei, int e) {
    int i = blockIdx.x * blockDim.x + threadIdx.x;
    if (i < e) {
        int s = load_idx(ei, i);
        int d = load_idx(ei, e + i);
        int pos = g_rs[d] + atomicAdd(&g_cur[d], 1);
        g_csr[pos] = s;
    }
}

// ---------------------------------------------------------------------------
// GEMM1 on tensor cores (mma.sync m16n8k16, fp16 split-precision 3 passes):
// h' = dinv * (x @ W1), stored fp16.
// CTA tile 64x128, full K=128 in smem. 8 warps = 2(M) x 4(N), warp m32 x n32.
// Swizzled smem (16B chunk index XOR row&7), rows exactly 256B -> 96KB total
// -> 2 CTAs/SM.
// ---------------------------------------------------------------------------
#define A_HI_OFF 0
#define A_LO_OFF 16384
#define W_HI_OFF 32768
#define W_LO_OFF 65536
#define SM1_TOT  98304

__global__ void __launch_bounds__(256, 2) k_gemm1_mma(
    const float* __restrict__ x, int n) {
    extern __shared__ char smem[];
    uint32_t sb = smem_u32(smem);
    int tid = threadIdx.x, wid = tid >> 5, lane = tid & 31;
    int row0 = blockIdx.x * 64;
    int wm = wid & 1, wn = wid >> 1;

    // stage W^T hi/lo, swizzled (L2-resident source)
    for (int t = tid; t < 128 * 16; t += 256) {
        int r = t >> 4, c = t & 15;
        int dst = r * 256 + ((c ^ (r & 7)) << 4);
        *(uint4*)(smem + W_HI_OFF + dst) = *(const uint4*)&g_wthi[r * DIN + c * 8];
        *(uint4*)(smem + W_LO_OFF + dst) = *(const uint4*)&g_wtlo[r * DIN + c * 8];
    }

    // stage A: load x fp32, split into fp16 hi/lo, swizzled
    for (int t = tid; t < 64 * 16; t += 256) {
        int r = t >> 4, c = t & 15;
        int c8 = c * 8;
        int gr = row0 + r;
        float v[8];
        if (gr < n) {
            float4 f0 = *(const float4*)&x[gr * DIN + c8];
            float4 f1 = *(const float4*)&x[gr * DIN + c8 + 4];
            v[0] = f0.x; v[1] = f0.y; v[2] = f0.z; v[3] = f0.w;
            v[4] = f1.x; v[5] = f1.y; v[6] = f1.z; v[7] = f1.w;
        } else {
#pragma unroll
            for (int q = 0; q < 8; q++) v[q] = 0.0f;
        }
        uint32_t hw[4], lw[4];
#pragma unroll
        for (int q = 0; q < 4; q++) {
            __half2 h2 = __floats2half2_rn(v[2 * q], v[2 * q + 1]);
            float2 hf = __half22float2(h2);
            __half2 l2 = __floats2half2_rn(v[2 * q] - hf.x, v[2 * q + 1] - hf.y);
            hw[q] = *(uint32_t*)&h2;
            lw[q] = *(uint32_t*)&l2;
        }
        int dst = r * 256 + ((c ^ (r & 7)) << 4);
        *(uint4*)(smem + A_HI_OFF + dst) = make_uint4(hw[0], hw[1], hw[2], hw[3]);
        *(uint4*)(smem + A_LO_OFF + dst) = make_uint4(lw[0], lw[1], lw[2], lw[3]);
    }
    __syncthreads();

    // ldmatrix per-lane row/chunk (swizzled addressing)
    int rowb = lane & 7, blk = lane >> 3;
    int mlrow[2], c0A = blk >> 1;
#pragma unroll
    for (int mi = 0; mi < 2; mi++)
        mlrow[mi] = (wm * 32 + mi * 16 + (blk & 1) * 8 + rowb) * 256;
    int nlrow[2], c0B = blk & 1;
#pragma unroll
    for (int p = 0; p < 2; p++)
        nlrow[p] = (wn * 32 + p * 16 + (blk >> 1) * 8 + rowb) * 256;

    float acc[2][4][4];
#pragma unroll
    for (int mi = 0; mi < 2; mi++)
#pragma unroll
        for (int nj = 0; nj < 4; nj++)
#pragma unroll
            for (int q = 0; q < 4; q++) acc[mi][nj][q] = 0.0f;

    const uint32_t aBase[3] = { sb + A_HI_OFF, sb + A_LO_OFF, sb + A_HI_OFF };
    const uint32_t bBase[3] = { sb + W_HI_OFF, sb + W_HI_OFF, sb + W_LO_OFF };

#pragma unroll
    for (int pass = 0; pass < 3; pass++) {
        uint32_t ab = aBase[pass], bb = bBase[pass];
#pragma unroll
        for (int ks = 0; ks < 8; ks++) {
            uint32_t a[2][4], b[2][4];
            int chA = ((c0A + 2 * ks) ^ rowb) << 4;
            int chB = ((c0B + 2 * ks) ^ rowb) << 4;
#pragma unroll
            for (int mi = 0; mi < 2; mi++)
                asm volatile("ldmatrix.sync.aligned.m8n8.x4.shared.b16 {%0,%1,%2,%3}, [%4];"
                             : "=r"(a[mi][0]), "=r"(a[mi][1]), "=r"(a[mi][2]), "=r"(a[mi][3])
                             : "r"(ab + (uint32_t)(mlrow[mi] + chA)));
#pragma unroll
            for (int p = 0; p < 2; p++)
                asm volatile("ldmatrix.sync.aligned.m8n8.x4.shared.b16 {%0,%1,%2,%3}, [%4];"
                             : "=r"(b[p][0]), "=r"(b[p][1]), "=r"(b[p][2]), "=r"(b[p][3])
                             : "r"(bb + (uint32_t)(nlrow[p] + chB)));
#pragma unroll
            for (int mi = 0; mi < 2; mi++)
#pragma unroll
                for (int nj = 0; nj < 4; nj++) {
                    uint32_t b0 = b[nj >> 1][(nj & 1) * 2];
                    uint32_t b1 = b[nj >> 1][(nj & 1) * 2 + 1];
                    asm volatile(
                        "mma.sync.aligned.m16n8k16.row.col.f32.f16.f16.f32 "
                        "{%0,%1,%2,%3}, {%4,%5,%6,%7}, {%8,%9}, {%0,%1,%2,%3};"
                        : "+f"(acc[mi][nj][0]), "+f"(acc[mi][nj][1]),
                          "+f"(acc[mi][nj][2]), "+f"(acc[mi][nj][3])
                        : "r"(a[mi][0]), "r"(a[mi][1]), "r"(a[mi][2]), "r"(a[mi][3]),
                          "r"(b0), "r"(b1));
                }
        }
    }

    // epilogue: dinv scale, pack half2, store h'
    int qr = lane >> 2, qc = (lane & 3) * 2;
#pragma unroll
    for (int mi = 0; mi < 2; mi++) {
        int r0 = row0 + wm * 32 + mi * 16 + qr;
        int r1 = r0 + 8;
        float dv0 = (r0 < n) ? g_dinv[r0] : 0.0f;
        float dv1 = (r1 < n) ? g_dinv[r1] : 0.0f;
#pragma unroll
        for (int nj = 0; nj < 4; nj++) {
            int col = wn * 32 + nj * 8 + qc;
            if (r0 < n) {
                __half2 p = __floats2half2_rn(dv0 * acc[mi][nj][0], dv0 * acc[mi][nj][1]);
                *(__half2*)&g_h16[r0 * DH + col] = p;
            }
            if (r1 < n) {
                __half2 p = __floats2half2_rn(dv1 * acc[mi][nj][2], dv1 * acc[mi][nj][3]);
                *(__half2*)&g_h16[r1 * DH + col] = p;
            }
        }
    }
}

// ---------------------------------------------------------------------------
// Gather layer 1: half-warp per node (2 nodes/warp). Sub-lane owns 8 halfs
// (uint4 = LDG.128). agg[v] = h'[v] + sum h'[src], fp32 accum, fp16 store.
// ---------------------------------------------------------------------------
__global__ void k_gather1(int n) {
    int gw = (blockIdx.x * blockDim.x + threadIdx.x) >> 5;
    int lane = threadIdx.x & 31;
    int w = gw * 2 + (lane >> 4);
    int sub = lane & 15;
    if (w >= n) return;
    int row = g_rs[w];
    int deg = g_cnt[w];
    const __half* hp = g_h16 + sub * 8;

    uint4 hv = *(const uint4*)&hp[w * DH];
    float2 f0 = __half22float2(*(__half2*)&hv.x);
    float2 f1 = __half22float2(*(__half2*)&hv.y);
    float2 f2 = __half22float2(*(__half2*)&hv.z);
    float2 f3 = __half22float2(*(__half2*)&hv.w);
    float a0 = f0.x, a1 = f0.y, a2 = f1.x, a3 = f1.y;
    float a4 = f2.x, a5 = f2.y, a6 = f3.x, a7 = f3.y;

    int j = 0;
    for (; j + 1 < deg; j += 2) {
        int s0 = g_csr[row + j];
        int s1 = g_csr[row + j + 1];
        uint4 u0 = *(const uint4*)&hp[s0 * DH];
        uint4 u1 = *(const uint4*)&hp[s1 * DH];
        float2 x0 = __half22float2(*(__half2*)&u0.x);
        float2 x1 = __half22float2(*(__half2*)&u0.y);
        float2 x2 = __half22float2(*(__half2*)&u0.z);
        float2 x3 = __half22float2(*(__half2*)&u0.w);
        float2 y0 = __half22float2(*(__half2*)&u1.x);
        float2 y1 = __half22float2(*(__half2*)&u1.y);
        float2 y2 = __half22float2(*(__half2*)&u1.z);
        float2 y3 = __half22float2(*(__half2*)&u1.w);
        a0 += x0.x + y0.x; a1 += x0.y + y0.y;
        a2 += x1.x + y1.x; a3 += x1.y + y1.y;
        a4 += x2.x + y2.x; a5 += x2.y + y2.y;
        a6 += x3.x + y3.x; a7 += x3.y + y3.y;
    }
    if (j < deg) {
        int s0 = g_csr[row + j];
        uint4 u0 = *(const uint4*)&hp[s0 * DH];
        float2 x0 = __half22float2(*(__half2*)&u0.x);
        float2 x1 = __half22float2(*(__half2*)&u0.y);
        float2 x2 = __half22float2(*(__half2*)&u0.z);
        float2 x3 = __half22float2(*(__half2*)&u0.w);
        a0 += x0.x; a1 += x0.y; a2 += x1.x; a3 += x1.y;
        a4 += x2.x; a5 += x2.y; a6 += x3.x; a7 += x3.y;
    }

    __half2 p0 = __floats2half2_rn(a0, a1);
    __half2 p1 = __floats2half2_rn(a2, a3);
    __half2 p2 = __floats2half2_rn(a4, a5);
    __half2 p3 = __floats2half2_rn(a6, a7);
    uint4 pk;
    pk.x = *(uint32_t*)&p0; pk.y = *(uint32_t*)&p1;
    pk.z = *(uint32_t*)&p2; pk.w = *(uint32_t*)&p3;
    *(uint4*)&g_agg16[w * DH + sub * 8] = pk;
}

// ---------------------------------------------------------------------------
// GEMM2 fused: h2 = relu(dinv*agg + b1); g' = dinv * (h2 @ W2) -> g_g
// ---------------------------------------------------------------------------
__global__ void __launch_bounds__(256) k_gemm2(
    const float* __restrict__ W2, const float* __restrict__ b1, int n) {
    __shared__ float Hs[64][129];
    __shared__ float Ws[128][16];

    int tid  = threadIdx.x;
    int row0 = blockIdx.x * 64;

    for (int i = tid; i < DH * DOUT; i += 256) Ws[i >> 4][i & 15] = W2[i];

    for (int t = tid; t < 64 * DH / 4; t += 256) {
        int r = t >> 5, c4 = (t & 31) * 4;
        int gr = row0 + r;
        float v0 = 0.f, v1 = 0.f, v2 = 0.f, v3 = 0.f;
        if (gr < n) {
            float dv = g_dinv[gr];
            uint2 u = *(const uint2*)&g_agg16[gr * DH + c4];
            float2 q0 = __half22float2(*(__half2*)&u.x);
            float2 q1 = __half22float2(*(__half2*)&u.y);
            float4 bb = *(const float4*)&b1[c4];
            v0 = fmaxf(dv * q0.x + bb.x, 0.f);
            v1 = fmaxf(dv * q0.y + bb.y, 0.f);
            v2 = fmaxf(dv * q1.x + bb.z, 0.f);
            v3 = fmaxf(dv * q1.y + bb.w, 0.f);
        }
        Hs[r][c4] = v0; Hs[r][c4 + 1] = v1;
        Hs[r][c4 + 2] = v2; Hs[r][c4 + 3] = v3;
    }
    __syncthreads();

    int r  = tid >> 2;
    int j4 = tid & 3;
    int gr = row0 + r;
    if (gr >= n) return;

    float4 acc = make_float4(0.f, 0.f, 0.f, 0.f);
#pragma unroll
    for (int k = 0; k < DH; k++) {
        float a = Hs[r][k];
        float4 wv = *(const float4*)&Ws[k][j4 * 4];
        acc.x += a * wv.x; acc.y += a * wv.y;
        acc.z += a * wv.z; acc.w += a * wv.w;
    }
    float dv = g_dinv[gr];
    acc.x *= dv; acc.y *= dv; acc.z *= dv; acc.w *= dv;
    *(float4*)&g_g[gr * DOUT + j4 * 4] = acc;
}

// ---------------------------------------------------------------------------
// Gather layer 2 + epilogue: warp per node, 8 edges/iter x 4 lanes x float4.
// out[v] = dinv[v]*(g'[v] + sum g'[src]) + b2
// ---------------------------------------------------------------------------
__global__ void k_gather2(const float* __restrict__ b2,
                          float* __restrict__ out, int n) {
    int w = (blockIdx.x * blockDim.x + threadIdx.x) >> 5;
    int lane = threadIdx.x & 31;
    if (w >= n) return;
    int row = g_rs[w];
    int deg = g_cnt[w];
    int g = lane >> 2;
    int c = lane & 3;

    float4 acc = make_float4(0.f, 0.f, 0.f, 0.f);
    for (int base = 0; base < deg; base += 8) {
        int j = base + g;
        if (j < deg) {
            int s = g_csr[row + j];
            float4 v = *(const float4*)&g_g[s * DOUT + c * 4];
            acc.x += v.x; acc.y += v.y; acc.z += v.z; acc.w += v.w;
        }
    }
#pragma unroll
    for (int off = 4; off < 32; off <<= 1) {
        acc.x += __shfl_xor_sync(0xFFFFFFFF, acc.x, off);
        acc.y += __shfl_xor_sync(0xFFFFFFFF, acc.y, off);
        acc.z += __shfl_xor_sync(0xFFFFFFFF, acc.z, off);
        acc.w += __shfl_xor_sync(0xFFFFFFFF, acc.w, off);
    }
    if (lane < 4) {
        float4 self = *(const float4*)&g_g[w * DOUT + c * 4];
        float4 bb   = *(const float4*)&b2[c * 4];
        float dv = g_dinv[w];
        float4 o;
        o.x = dv * (acc.x + self.x) + bb.x;
        o.y = dv * (acc.y + self.y) + bb.y;
        o.z = dv * (acc.z + self.z) + bb.z;
        o.w = dv * (acc.w + self.w) + bb.w;
        *(float4*)&out[w * DOUT + c * 4] = o;
    }
}

// ---------------------------------------------------------------------------
extern "C" void kernel_launch(void* const* d_in, const int* in_sizes, int n_in,
                              void* d_out, int out_size) {
    const float* x  = (const float*)d_in[0];
    const void*  ei = d_in[1];
    const float* W1 = (const float*)d_in[2];
    const float* b1 = (const float*)d_in[3];
    const float* W2 = (const float*)d_in[4];
    const float* b2 = (const float*)d_in[5];
    float*       out = (float*)d_out;

    int n = in_sizes[0] / DIN;   // 100000
    int e = in_sizes[1] / 2;     // 1600000
    int nb = (n + 1023) >> 10;

    static int smem_set = 0;
    if (!smem_set) {
        cudaFuncSetAttribute(k_gemm1_mma,
                             cudaFuncAttributeMaxDynamicSharedMemorySize, SM1_TOT);
        smem_set = 1;
    }

    k_init<<<(n + 255) / 256, 256>>>((const int*)ei, W1, n);
    k_hist<<<(e + 255) / 256, 256>>>(ei, e);
    k_scan_block<<<nb, 1024>>>(n);
    k_scan_tot<<<1, 128>>>(nb);
    k_scan_add<<<(n + 255) / 256, 256>>>(n);
    k_fill<<<(e + 255) / 256, 256>>>(ei, e);

    k_gemm1_mma<<<(n + 63) / 64, 256, SM1_TOT>>>(x, n);
    {
        int warps = (n + 1) / 2;
        k_gather1<<<(warps * 32 + 255) / 256, 256>>>(n);
    }
    k_gemm2<<<(n + 63) / 64, 256>>>(W2, b1, n);
    k_gather2<<<(n * 32 + 255) / 256, 256>>>(b2, out, n);
}